// round 1
// baseline (speedup 1.0000x reference)
#include <cuda_runtime.h>

// SpikingMLP: out = (spike_rate(x @ w_up^T)) @ w_down^T, plus per-unit mean rate.
// Shapes (fixed): x [4096,1024], w_up [4096,1024], w_down [1024,4096], beta [4096], T=8.
// d_out = [out (4096*1024 floats)] ++ [rate_per_unit (4096 floats)].

namespace cfg {
constexpr int M  = 4096;   // B*S
constexpr int Dd = 1024;   // D
constexpr int Ff = 4096;   // F
}

// Scratch (static device allocation — allowed; runtime alloc is not).
__device__ float g_rate[(size_t)cfg::M * cfg::Ff];      // 64 MB
__device__ float g_partial[4 * cfg::Ff];

// C[M,N] = A[M,KDIM] * B[N,KDIM]^T   (both row-major, K contiguous)
// SPIKE epilogue: run T-step LIF recurrence on each h, store firing rate.
template<int KDIM, bool SPIKE>
__global__ __launch_bounds__(256, 2)
void sgemm_kernel(const float* __restrict__ A, const float* __restrict__ B,
                  float* __restrict__ C, int ldc,
                  const float* __restrict__ beta, const int* __restrict__ Tptr)
{
    __shared__ float As[8][132];   // +4 pad: conflict-free transposed stores
    __shared__ float Bs[8][132];

    const int tid = threadIdx.x;
    const int tx = tid & 15;        // 16 x 16 thread grid, 8x8 microtile
    const int ty = tid >> 4;
    const int rowBase = blockIdx.y * 128;
    const int colBase = blockIdx.x * 128;

    const int lrow = tid >> 1;      // 0..127
    const int lk   = (tid & 1) * 4; // 0 or 4

    const float* Aptr = A + (size_t)(rowBase + lrow) * KDIM + lk;
    const float* Bptr = B + (size_t)(colBase + lrow) * KDIM + lk;

    float acc[8][8];
    #pragma unroll
    for (int i = 0; i < 8; i++)
        #pragma unroll
        for (int j = 0; j < 8; j++) acc[i][j] = 0.0f;

    for (int k0 = 0; k0 < KDIM; k0 += 8) {
        float4 av = *(const float4*)(Aptr + k0);
        float4 bv = *(const float4*)(Bptr + k0);
        __syncthreads();
        As[lk + 0][lrow] = av.x; As[lk + 1][lrow] = av.y;
        As[lk + 2][lrow] = av.z; As[lk + 3][lrow] = av.w;
        Bs[lk + 0][lrow] = bv.x; Bs[lk + 1][lrow] = bv.y;
        Bs[lk + 2][lrow] = bv.z; Bs[lk + 3][lrow] = bv.w;
        __syncthreads();
        #pragma unroll
        for (int k = 0; k < 8; k++) {
            float a[8], b[8];
            *(float4*)(a)     = *(const float4*)(&As[k][ty * 8]);
            *(float4*)(a + 4) = *(const float4*)(&As[k][ty * 8 + 4]);
            *(float4*)(b)     = *(const float4*)(&Bs[k][tx * 8]);
            *(float4*)(b + 4) = *(const float4*)(&Bs[k][tx * 8 + 4]);
            #pragma unroll
            for (int i = 0; i < 8; i++)
                #pragma unroll
                for (int j = 0; j < 8; j++)
                    acc[i][j] += a[i] * b[j];
        }
    }

    if (SPIKE) {
        const int T = Tptr ? *Tptr : 8;       // scalar input (LE low word)
        const float invT = 1.0f / (float)T;
        float bet[8];
        #pragma unroll
        for (int j = 0; j < 8; j++) bet[j] = beta[colBase + tx * 8 + j];
        #pragma unroll
        for (int i = 0; i < 8; i++) {
            float r[8];
            #pragma unroll
            for (int j = 0; j < 8; j++) {
                const float h = acc[i][j];
                float v = 0.0f;
                int cnt = 0;
                for (int t = 0; t < T; t++) {
                    v = bet[j] * v + h;       // leaky integrate
                    if (v > 1.0f) { cnt++; v -= 1.0f; }  // fire + soft reset
                }
                r[j] = (float)cnt * invT;
            }
            float* cptr = C + (size_t)(rowBase + ty * 8 + i) * ldc + colBase + tx * 8;
            *(float4*)(cptr)     = *(const float4*)(r);
            *(float4*)(cptr + 4) = *(const float4*)(r + 4);
        }
    } else {
        #pragma unroll
        for (int i = 0; i < 8; i++) {
            float* cptr = C + (size_t)(rowBase + ty * 8 + i) * ldc + colBase + tx * 8;
            *(float4*)(cptr)     = *(const float4*)(&acc[i][0]);
            *(float4*)(cptr + 4) = *(const float4*)(&acc[i][4]);
        }
    }
}

// Column sums of g_rate in 4 row-chunks (coalesced, no atomics).
__global__ void colsum_partial_kernel()
{
    const int f  = blockIdx.x * 256 + threadIdx.x;
    const int r0 = blockIdx.y * (cfg::M / 4);
    float s0 = 0.f, s1 = 0.f, s2 = 0.f, s3 = 0.f;
    for (int m = 0; m < cfg::M / 4; m += 4) {
        s0 += g_rate[(size_t)(r0 + m + 0) * cfg::Ff + f];
        s1 += g_rate[(size_t)(r0 + m + 1) * cfg::Ff + f];
        s2 += g_rate[(size_t)(r0 + m + 2) * cfg::Ff + f];
        s3 += g_rate[(size_t)(r0 + m + 3) * cfg::Ff + f];
    }
    g_partial[blockIdx.y * cfg::Ff + f] = (s0 + s1) + (s2 + s3);
}

__global__ void colsum_final_kernel(float* __restrict__ outv)
{
    const int f = blockIdx.x * 256 + threadIdx.x;
    const float s = (g_partial[f] + g_partial[cfg::Ff + f]) +
                    (g_partial[2 * cfg::Ff + f] + g_partial[3 * cfg::Ff + f]);
    outv[f] = s * (1.0f / (float)cfg::M);   // exact: sums are multiples of 1/8 < 2^21
}

extern "C" void kernel_launch(void* const* d_in, const int* in_sizes, int n_in,
                              void* d_out, int out_size)
{
    const float* x      = (const float*)d_in[0];
    const float* w_up   = (const float*)d_in[1];
    const float* w_down = (const float*)d_in[2];
    const float* beta   = (const float*)d_in[3];
    const int*   Tptr   = (n_in > 4) ? (const int*)d_in[4] : nullptr;

    float* out = (float*)d_out;
    float* rpu = out + (size_t)cfg::M * cfg::Dd;

    float* rate = nullptr;
    cudaGetSymbolAddress((void**)&rate, g_rate);

    // GEMM1 fused with spike recurrence -> rate
    sgemm_kernel<cfg::Dd, true>
        <<<dim3(cfg::Ff / 128, cfg::M / 128), 256>>>(x, w_up, rate, cfg::Ff, beta, Tptr);

    // per-unit firing rate
    colsum_partial_kernel<<<dim3(cfg::Ff / 256, 4), 256>>>();
    colsum_final_kernel<<<cfg::Ff / 256, 256>>>(rpu);

    // GEMM2: out = rate @ w_down^T
    sgemm_kernel<cfg::Ff, false>
        <<<dim3(cfg::Dd / 128, cfg::M / 128), 256>>>(rate, w_down, out, cfg::Dd, nullptr, nullptr);
}

// round 3
// speedup vs baseline: 1.5432x; 1.5432x over previous
#include <cuda_runtime.h>
#include <cstdint>

// SpikingMLP via mma.sync.m16n8k8 TF32 (legacy tensor path, works on plain sm_100).
//   rate = spike_rate(x @ w_up^T)   : 3xTF32 split (Ah*Bh + Ah*Bl + Al*Bh)
//   out  = rate @ w_down^T          : 2xTF32 split (rate is tf32-exact)
//   rate_per_unit = column mean of rate.

namespace cfg {
constexpr int M  = 4096;
constexpr int Dd = 1024;
constexpr int Ff = 4096;
}

__device__ float g_rate[(size_t)cfg::M * cfg::Ff];   // 64 MB scratch
__device__ float g_partial[4 * cfg::Ff];

// ------------------------------------------------------------------ helpers
__device__ __forceinline__ uint32_t f2tf32(float f) {
    uint32_t r;
    asm("cvt.rna.tf32.f32 %0, %1;" : "=r"(r) : "f"(f));
    return r;
}
__device__ __forceinline__ void mma_tf32(float c[4],
                                         uint32_t a0, uint32_t a1, uint32_t a2, uint32_t a3,
                                         uint32_t b0, uint32_t b1) {
    asm volatile(
        "mma.sync.aligned.m16n8k8.row.col.f32.tf32.tf32.f32 "
        "{%0,%1,%2,%3}, {%4,%5,%6,%7}, {%8,%9}, {%0,%1,%2,%3};"
        : "+f"(c[0]), "+f"(c[1]), "+f"(c[2]), "+f"(c[3])
        : "r"(a0), "r"(a1), "r"(a2), "r"(a3), "r"(b0), "r"(b1));
}
__device__ __forceinline__ void cp16(uint32_t sdst, const void* gsrc) {
    asm volatile("cp.async.cg.shared.global [%0], [%1], 16;" :: "r"(sdst), "l"(gsrc));
}
#define CP_COMMIT() asm volatile("cp.async.commit_group;" ::: "memory")
#define CP_WAIT1()  asm volatile("cp.async.wait_group 1;" ::: "memory")

__device__ __forceinline__ float spike_rate_of(float h, float be, int T, float invT) {
    float v = 0.0f; int cnt = 0;
    for (int t = 0; t < T; t++) {
        v = be * v + h;
        if (v > 1.0f) { cnt++; v -= 1.0f; }
    }
    return (float)cnt * invT;
}

// ------------------------------------------------------------------ main GEMM
// C[128x128] per CTA. A[M,KDIM], B[N,KDIM] row-major (K contiguous).
// NPASS==3: split A and B.  NPASS==2: A exact, split B.
template <int KDIM, int NPASS, bool SPIKE>
__global__ __launch_bounds__(256, 2)
void tc_gemm(const float* __restrict__ A, const float* __restrict__ B,
             float* __restrict__ C, int ldc,
             const float* __restrict__ beta, const int* __restrict__ Tptr)
{
    constexpr int LDSW  = 36;            // floats per smem row (32 + 4 pad)
    constexpr int TILEF = 128 * LDSW;    // floats per tile (18432 B)
    constexpr int NC    = KDIM / 32;
    extern __shared__ float sm[];        // [stage][A|B][TILEF]

    const int tid  = threadIdx.x;
    const int lane = tid & 31;
    const int wid  = tid >> 5;
    const int wm   = (wid & 1) * 64;     // warp M offset (2 warps over M)
    const int wn   = (wid >> 1) * 32;    // warp N offset (4 warps over N)
    const int gq   = lane >> 2;          // groupID 0..7
    const int tq   = lane & 3;           // threadID_in_group 0..3
    const int rowBase = blockIdx.y * 128;
    const int colBase = blockIdx.x * 128;

    // producer mapping: each thread copies 16 A floats + 16 B floats per chunk
    const int prow = tid >> 1;
    const int pcol = (tid & 1) * 16;
    const float* Ap = A + (size_t)(rowBase + prow) * KDIM + pcol;
    const float* Bp = B + (size_t)(colBase + prow) * KDIM + pcol;
    const uint32_t sbase = (uint32_t)__cvta_generic_to_shared(sm);
    const uint32_t pdst  = (uint32_t)(prow * LDSW + pcol) * 4;

    float acc[4][4][4];
    #pragma unroll
    for (int mi = 0; mi < 4; mi++)
        #pragma unroll
        for (int ni = 0; ni < 4; ni++)
            #pragma unroll
            for (int q = 0; q < 4; q++) acc[mi][ni][q] = 0.0f;

    // prologue: stage chunks 0,1
    #pragma unroll
    for (int s = 0; s < 2; s++) {
        uint32_t ad = sbase + (uint32_t)(s * 2 * TILEF) * 4 + pdst;
        uint32_t bd = ad + TILEF * 4;
        const float* ag = Ap + s * 32;
        const float* bg = Bp + s * 32;
        #pragma unroll
        for (int q = 0; q < 4; q++) { cp16(ad + q * 16, ag + q * 4); cp16(bd + q * 16, bg + q * 4); }
        CP_COMMIT();
    }

    for (int c = 0; c < NC; c++) {
        CP_WAIT1();
        __syncthreads();
        const float* a_s = sm + (c & 1) * 2 * TILEF;
        const float* b_s = a_s + TILEF;

        #pragma unroll
        for (int ks = 0; ks < 4; ks++) {
            const int k = ks * 8 + tq;
            // B fragments (raw -> split in regs)
            uint32_t bh[4][2], bl[4][2];
            #pragma unroll
            for (int ni = 0; ni < 4; ni++) {
                const int br = wn + ni * 8 + gq;
                float v0 = b_s[br * LDSW + k];
                float v1 = b_s[br * LDSW + k + 4];
                bh[ni][0] = f2tf32(v0); bh[ni][1] = f2tf32(v1);
                bl[ni][0] = f2tf32(v0 - __uint_as_float(bh[ni][0]));
                bl[ni][1] = f2tf32(v1 - __uint_as_float(bh[ni][1]));
            }
            #pragma unroll
            for (int mi = 0; mi < 4; mi++) {
                const int ar = wm + mi * 16 + gq;
                float u0 = a_s[ar * LDSW + k];
                float u1 = a_s[(ar + 8) * LDSW + k];
                float u2 = a_s[ar * LDSW + k + 4];
                float u3 = a_s[(ar + 8) * LDSW + k + 4];
                uint32_t ah0 = f2tf32(u0), ah1 = f2tf32(u1), ah2 = f2tf32(u2), ah3 = f2tf32(u3);
                uint32_t al0, al1, al2, al3;
                if (NPASS == 3) {
                    al0 = f2tf32(u0 - __uint_as_float(ah0));
                    al1 = f2tf32(u1 - __uint_as_float(ah1));
                    al2 = f2tf32(u2 - __uint_as_float(ah2));
                    al3 = f2tf32(u3 - __uint_as_float(ah3));
                }
                #pragma unroll
                for (int ni = 0; ni < 4; ni++) {
                    mma_tf32(acc[mi][ni], ah0, ah1, ah2, ah3, bh[ni][0], bh[ni][1]);
                    mma_tf32(acc[mi][ni], ah0, ah1, ah2, ah3, bl[ni][0], bl[ni][1]);
                    if (NPASS == 3)
                        mma_tf32(acc[mi][ni], al0, al1, al2, al3, bh[ni][0], bh[ni][1]);
                }
            }
        }

        __syncthreads();
        if (c + 2 < NC) {
            uint32_t ad = sbase + (uint32_t)((c & 1) * 2 * TILEF) * 4 + pdst;
            uint32_t bd = ad + TILEF * 4;
            const float* ag = Ap + (c + 2) * 32;
            const float* bg = Bp + (c + 2) * 32;
            #pragma unroll
            for (int q = 0; q < 4; q++) { cp16(ad + q * 16, ag + q * 4); cp16(bd + q * 16, bg + q * 4); }
        }
        CP_COMMIT();
    }

    // ---------------------------------------------------------------- epilogue
    const int T    = SPIKE ? *Tptr : 0;
    const float invT = SPIKE ? (1.0f / (float)T) : 0.0f;

    #pragma unroll
    for (int ni = 0; ni < 4; ni++) {
        const int cglob = colBase + wn + ni * 8 + 2 * tq;
        float be0 = 0.f, be1 = 0.f;
        if (SPIKE) { be0 = beta[cglob]; be1 = beta[cglob + 1]; }
        #pragma unroll
        for (int mi = 0; mi < 4; mi++) {
            const int r0 = rowBase + wm + mi * 16 + gq;
            float v00 = acc[mi][ni][0], v01 = acc[mi][ni][1];
            float v10 = acc[mi][ni][2], v11 = acc[mi][ni][3];
            if (SPIKE) {
                v00 = spike_rate_of(v00, be0, T, invT);
                v01 = spike_rate_of(v01, be1, T, invT);
                v10 = spike_rate_of(v10, be0, T, invT);
                v11 = spike_rate_of(v11, be1, T, invT);
            }
            float2 p0 = make_float2(v00, v01);
            float2 p1 = make_float2(v10, v11);
            *(float2*)(C + (size_t)r0 * ldc + cglob)       = p0;
            *(float2*)(C + (size_t)(r0 + 8) * ldc + cglob) = p1;
        }
    }
}

// ---------------------------------------------------------------- reductions
__global__ void colsum_partial_kernel()
{
    const int f  = blockIdx.x * 256 + threadIdx.x;
    const int r0 = blockIdx.y * (cfg::M / 4);
    float s0 = 0.f, s1 = 0.f, s2 = 0.f, s3 = 0.f;
    for (int m = 0; m < cfg::M / 4; m += 4) {
        s0 += g_rate[(size_t)(r0 + m + 0) * cfg::Ff + f];
        s1 += g_rate[(size_t)(r0 + m + 1) * cfg::Ff + f];
        s2 += g_rate[(size_t)(r0 + m + 2) * cfg::Ff + f];
        s3 += g_rate[(size_t)(r0 + m + 3) * cfg::Ff + f];
    }
    g_partial[blockIdx.y * cfg::Ff + f] = (s0 + s1) + (s2 + s3);
}

__global__ void colsum_final_kernel(float* __restrict__ outv)
{
    const int f = blockIdx.x * 256 + threadIdx.x;
    const float s = (g_partial[f] + g_partial[cfg::Ff + f]) +
                    (g_partial[2 * cfg::Ff + f] + g_partial[3 * cfg::Ff + f]);
    outv[f] = s * (1.0f / (float)cfg::M);
}

// -------------------------------------------------------------------- launch
extern "C" void kernel_launch(void* const* d_in, const int* in_sizes, int n_in,
                              void* d_out, int out_size)
{
    const float* x      = (const float*)d_in[0];
    const float* w_up   = (const float*)d_in[1];
    const float* w_down = (const float*)d_in[2];
    const float* beta   = (const float*)d_in[3];
    const int*   Tptr   = (const int*)d_in[4];

    float* out = (float*)d_out;
    float* rpu = out + (size_t)cfg::M * cfg::Dd;

    float* rate = nullptr;
    cudaGetSymbolAddress((void**)&rate, g_rate);

    constexpr int SMEM = 2 * 2 * 128 * 36 * 4;   // 73728 B
    cudaFuncSetAttribute(tc_gemm<cfg::Dd, 3, true>,
                         cudaFuncAttributeMaxDynamicSharedMemorySize, SMEM);
    cudaFuncSetAttribute(tc_gemm<cfg::Ff, 2, false>,
                         cudaFuncAttributeMaxDynamicSharedMemorySize, SMEM);

    // GEMM1 + spike epilogue -> g_rate
    tc_gemm<cfg::Dd, 3, true>
        <<<dim3(cfg::Ff / 128, cfg::M / 128), 256, SMEM>>>(x, w_up, rate, cfg::Ff, beta, Tptr);

    // per-unit firing rate
    colsum_partial_kernel<<<dim3(cfg::Ff / 256, 4), 256>>>();
    colsum_final_kernel<<<cfg::Ff / 256, 256>>>(rpu);

    // GEMM2: out = rate @ w_down^T
    tc_gemm<cfg::Ff, 2, false>
        <<<dim3(cfg::Dd / 128, cfg::M / 128), 256, SMEM>>>(rate, w_down, out, cfg::Dd, nullptr, nullptr);
}